// round 5
// baseline (speedup 1.0000x reference)
#include <cuda_runtime.h>
#include <cstdint>

#define BB 8
#define NN 16384
#define FF 64
#define EE 262144
#define CC 10
#define BN_EPS 1e-5f

// ---------------- device scratch (no allocs; zero-initialized at load) ----------------
__device__ int    g_deg_out[BB * NN];      // zeroed by k_scan after use
__device__ int    g_deg_in [BB * NN];      // zeroed by k_scan after use
__device__ int    g_cursor [BB * NN];
__device__ float  g_rs_out [BB * NN];
__device__ float  g_rs_in  [BB * NN];
__device__ int    g_row_off[BB * (NN + 1)];
__device__ int    g_esrt   [(size_t)BB * EE];   // src indices sorted by dst
__device__ float  g_xs [(size_t)BB * NN * FF];  // x * rs_out  (conv1 input)
__device__ float  g_h1 [(size_t)BB * NN * FF];  // relu(conv1) * rs_out (conv2 input)
__device__ float  g_h2 [(size_t)BB * NN * FF];  // conv2 output
__device__ float  g_bn_sum [2 * FF];            // zeroed by k_bncoef after use
__device__ float  g_bn_coef[2 * FF];

// ---------------- kernels ----------------

__global__ void k_degree(const int* __restrict__ src, const int* __restrict__ dst) {
    int i = blockIdx.x * blockDim.x + threadIdx.x;   // BB*EE
    int b = i >> 18;                                  // EE = 2^18
    atomicAdd(&g_deg_out[b * NN + src[i]], 1);
    atomicAdd(&g_deg_in [b * NN + dst[i]], 1);
}

// one block per batch, 1024 threads, 16 nodes/thread.
// Exclusive scan of deg_in -> row_off + cursor; rs_in/rs_out; re-zero deg arrays.
__global__ __launch_bounds__(1024) void k_scan() {
    __shared__ int warpsum[32];
    int b = blockIdx.x, t = threadIdx.x;
    int lane = t & 31, wid = t >> 5;
    int base = b * NN + t * 16;
    int loc[16];
    int sum = 0;
#pragma unroll
    for (int i = 0; i < 16; i++) {
        int d = g_deg_in[base + i];
        loc[i] = sum; sum += d;
        g_rs_in[base + i] = rsqrtf((float)(d < 1 ? 1 : d));
        int dgo = g_deg_out[base + i];
        g_rs_out[base + i] = rsqrtf((float)(dgo < 1 ? 1 : dgo));
        g_deg_in[base + i]  = 0;                      // reset for next replay
        g_deg_out[base + i] = 0;
    }
    int v = sum;
#pragma unroll
    for (int off = 1; off < 32; off <<= 1) {
        int u = __shfl_up_sync(0xFFFFFFFFu, v, off);
        if (lane >= off) v += u;
    }
    if (lane == 31) warpsum[wid] = v;
    __syncthreads();
    if (wid == 0) {
        int w = warpsum[lane];
#pragma unroll
        for (int off = 1; off < 32; off <<= 1) {
            int u = __shfl_up_sync(0xFFFFFFFFu, w, off);
            if (lane >= off) w += u;
        }
        warpsum[lane] = w;
    }
    __syncthreads();
    int wbase = (wid == 0) ? 0 : warpsum[wid - 1];
    int excl  = wbase + v - sum;
    int ob = b * (NN + 1) + t * 16;
#pragma unroll
    for (int i = 0; i < 16; i++) {
        int o = excl + loc[i];
        g_row_off[ob + i] = o;
        g_cursor[base + i] = o;
    }
    if (t == 1023) g_row_off[b * (NN + 1) + NN] = excl + sum;
}

// bucket-fill sorted-by-dst src list (4B scatter) + prescale xs = x * rs_out
__global__ void k_fill(const int* __restrict__ src, const int* __restrict__ dst,
                       const float* __restrict__ x) {
    int i = blockIdx.x * blockDim.x + threadIdx.x;   // BB*EE == BB*NN*FF/4 == 2M
    int b = i >> 18;
    int s = src[i];
    int d = dst[i];
    int pos = atomicAdd(&g_cursor[b * NN + d], 1);
    g_esrt[(size_t)b * EE + pos] = s;

    // prescale chore: one float4 per thread
    float sc = g_rs_out[i >> 4];                      // (i*4)/FF
    float4 vx = __ldg((const float4*)x + i);
    vx.x *= sc; vx.y *= sc; vx.z *= sc; vx.w *= sc;
    ((float4*)g_xs)[i] = vx;
}

// Fused: CSR gather-sum + [32,64]x[64,64] GEMM + bias (+relu, +rs_out prescale for next conv)
// 256 threads, 32 nodes per CTA. phase 0: xs -> h1 (relu*rs_out). phase 1: h1 -> h2.
__global__ __launch_bounds__(256) void k_conv(const float* __restrict__ W,
                                              const float* __restrict__ bias,
                                              int phase) {
    __shared__ float sW[64 * 64];
    __shared__ float sT[64][33];                      // [k][node], padded

    const float* in  = (phase == 0) ? g_xs : g_h1;
    float*       out = (phase == 0) ? g_h1 : g_h2;

    int t  = threadIdx.x;
    int cb = blockIdx.x;
    int b  = cb >> 9;                                 // 512 CTAs per batch
    int n0 = (cb & 511) << 5;

    for (int i = t; i < 64 * 64; i += 256) sW[i] = W[i];

    // ---- gather: 8 threads per node, 8 features each ----
    int nl = t >> 3;
    int f0 = (t & 7) << 3;
    int n  = n0 + nl;
    const float* inb = in + (size_t)b * NN * FF;
    const int*   es  = g_esrt + (size_t)b * EE;
    int r0 = g_row_off[b * (NN + 1) + n];
    int r1 = g_row_off[b * (NN + 1) + n + 1];

    float4 a0 = make_float4(0.f, 0.f, 0.f, 0.f);
    float4 a1 = make_float4(0.f, 0.f, 0.f, 0.f);
    int e = r0;
    for (; e + 4 <= r1; e += 4) {
        int s0 = __ldg(es + e);
        int s1 = __ldg(es + e + 1);
        int s2 = __ldg(es + e + 2);
        int s3 = __ldg(es + e + 3);
        const float4* q0 = (const float4*)(inb + (size_t)s0 * FF + f0);
        const float4* q1 = (const float4*)(inb + (size_t)s1 * FF + f0);
        const float4* q2 = (const float4*)(inb + (size_t)s2 * FF + f0);
        const float4* q3 = (const float4*)(inb + (size_t)s3 * FF + f0);
        float4 v0 = __ldg(q0), v1 = __ldg(q0 + 1);
        float4 v2 = __ldg(q1), v3 = __ldg(q1 + 1);
        float4 v4 = __ldg(q2), v5 = __ldg(q2 + 1);
        float4 v6 = __ldg(q3), v7 = __ldg(q3 + 1);
        a0.x += v0.x + v2.x; a0.y += v0.y + v2.y;
        a0.z += v0.z + v2.z; a0.w += v0.w + v2.w;
        a1.x += v1.x + v3.x; a1.y += v1.y + v3.y;
        a1.z += v1.z + v3.z; a1.w += v1.w + v3.w;
        a0.x += v4.x + v6.x; a0.y += v4.y + v6.y;
        a0.z += v4.z + v6.z; a0.w += v4.w + v6.w;
        a1.x += v5.x + v7.x; a1.y += v5.y + v7.y;
        a1.z += v5.z + v7.z; a1.w += v5.w + v7.w;
    }
    for (; e < r1; e++) {
        int s0 = __ldg(es + e);
        const float4* q0 = (const float4*)(inb + (size_t)s0 * FF + f0);
        float4 v0 = __ldg(q0), v1 = __ldg(q0 + 1);
        a0.x += v0.x; a0.y += v0.y; a0.z += v0.z; a0.w += v0.w;
        a1.x += v1.x; a1.y += v1.y; a1.z += v1.z; a1.w += v1.w;
    }
    float si = g_rs_in[b * NN + n];
    a0.x *= si; a0.y *= si; a0.z *= si; a0.w *= si;
    a1.x *= si; a1.y *= si; a1.z *= si; a1.w *= si;

    sT[f0 + 0][nl] = a0.x; sT[f0 + 1][nl] = a0.y;
    sT[f0 + 2][nl] = a0.z; sT[f0 + 3][nl] = a0.w;
    sT[f0 + 4][nl] = a1.x; sT[f0 + 5][nl] = a1.y;
    sT[f0 + 6][nl] = a1.z; sT[f0 + 7][nl] = a1.w;
    __syncthreads();

    // ---- GEMM: each thread computes 2 nodes x 4 features ----
    int nn = (t >> 4) << 1;
    int q  = (t & 15) << 2;
    float4 c0 = make_float4(0.f, 0.f, 0.f, 0.f);
    float4 c1 = make_float4(0.f, 0.f, 0.f, 0.f);
#pragma unroll
    for (int k = 0; k < 64; k++) {
        float x0 = sT[k][nn];
        float x1 = sT[k][nn + 1];
        float4 w = *(const float4*)&sW[k * 64 + q];
        c0.x = fmaf(x0, w.x, c0.x); c0.y = fmaf(x0, w.y, c0.y);
        c0.z = fmaf(x0, w.z, c0.z); c0.w = fmaf(x0, w.w, c0.w);
        c1.x = fmaf(x1, w.x, c1.x); c1.y = fmaf(x1, w.y, c1.y);
        c1.z = fmaf(x1, w.z, c1.z); c1.w = fmaf(x1, w.w, c1.w);
    }
    float4 bv = __ldg((const float4*)(bias + q));
    c0.x += bv.x; c0.y += bv.y; c0.z += bv.z; c0.w += bv.w;
    c1.x += bv.x; c1.y += bv.y; c1.z += bv.z; c1.w += bv.w;
    if (phase == 0) {
        // relu then prescale by rs_out for the next conv's gather
        float s0 = g_rs_out[b * NN + n0 + nn];
        float s1 = g_rs_out[b * NN + n0 + nn + 1];
        c0.x = fmaxf(c0.x, 0.f) * s0; c0.y = fmaxf(c0.y, 0.f) * s0;
        c0.z = fmaxf(c0.z, 0.f) * s0; c0.w = fmaxf(c0.w, 0.f) * s0;
        c1.x = fmaxf(c1.x, 0.f) * s1; c1.y = fmaxf(c1.y, 0.f) * s1;
        c1.z = fmaxf(c1.z, 0.f) * s1; c1.w = fmaxf(c1.w, 0.f) * s1;
    }
    *(float4*)(out + ((size_t)b * NN + n0 + nn)     * FF + q) = c0;
    *(float4*)(out + ((size_t)b * NN + n0 + nn + 1) * FF + q) = c1;
}

__global__ __launch_bounds__(256) void k_bnstats() {
    int tid = blockIdx.x * 256 + threadIdx.x;
    int stride = gridDim.x * 256;                    // multiple of 16
    const float4* h = (const float4*)g_h2;
    float4 s = make_float4(0.f, 0.f, 0.f, 0.f);
    float4 q = make_float4(0.f, 0.f, 0.f, 0.f);
    for (int i = tid; i < BB * NN * FF / 4; i += stride) {
        float4 v = __ldg(h + i);
        s.x += v.x; s.y += v.y; s.z += v.z; s.w += v.w;
        q.x = fmaf(v.x, v.x, q.x); q.y = fmaf(v.y, v.y, q.y);
        q.z = fmaf(v.z, v.z, q.z); q.w = fmaf(v.w, v.w, q.w);
    }
    int f0 = (tid & 15) * 4;
    __shared__ float sh[128];
    if (threadIdx.x < 128) sh[threadIdx.x] = 0.f;
    __syncthreads();
    atomicAdd(&sh[f0 + 0], s.x); atomicAdd(&sh[f0 + 1], s.y);
    atomicAdd(&sh[f0 + 2], s.z); atomicAdd(&sh[f0 + 3], s.w);
    atomicAdd(&sh[64 + f0 + 0], q.x); atomicAdd(&sh[64 + f0 + 1], q.y);
    atomicAdd(&sh[64 + f0 + 2], q.z); atomicAdd(&sh[64 + f0 + 3], q.w);
    __syncthreads();
    if (threadIdx.x < 128) atomicAdd(&g_bn_sum[threadIdx.x], sh[threadIdx.x]);
}

// coef computation + bn_sum reset + output bias init (128 threads)
__global__ void k_bncoef(const float* __restrict__ gamma, const float* __restrict__ beta,
                         const float* __restrict__ lin_b, float* __restrict__ out) {
    int t = threadIdx.x;
    if (t < 64) {
        const float inv_n = 1.0f / (float)(BB * NN);
        float s  = g_bn_sum[t];
        float s2 = g_bn_sum[64 + t];
        float mean = s * inv_n;
        float var  = s2 * inv_n - mean * mean;
        float scale = gamma[t] * rsqrtf(var + BN_EPS);
        g_bn_coef[t]      = scale;
        g_bn_coef[64 + t] = beta[t] - mean * scale;
        g_bn_sum[t] = 0.0f;                           // reset for next replay
        g_bn_sum[64 + t] = 0.0f;
    }
    if (t < 80) out[t] = lin_b[t % CC];
}

// out[b][c] += sum_i (h2[b][i]*scale[f]+shift[f]) * lin_W[c][i]
__global__ __launch_bounds__(256) void k_final(const float* __restrict__ linW,
                                               float* __restrict__ out) {
    __shared__ float cf[128];
    if (threadIdx.x < 128) cf[threadIdx.x] = g_bn_coef[threadIdx.x];
    __syncthreads();

    int tid = blockIdx.x * 256 + threadIdx.x;
    int stride = gridDim.x * 256;                    // multiple of 16
    const int NI4 = NN * FF / 4;
    float acc[BB][CC];
#pragma unroll
    for (int b = 0; b < BB; b++)
#pragma unroll
        for (int c = 0; c < CC; c++) acc[b][c] = 0.f;

    const float4* h4 = (const float4*)g_h2;
    const float4* w4 = (const float4*)linW;
    for (int i = tid; i < NI4; i += stride) {
        int f0 = (i & 15) * 4;
        float4 sc  = *(const float4*)&cf[f0];
        float4 sh4 = *(const float4*)&cf[64 + f0];
        float4 hv[BB];
#pragma unroll
        for (int b = 0; b < BB; b++) {
            float4 v = __ldg(h4 + (size_t)b * NI4 + i);
            hv[b].x = fmaf(v.x, sc.x, sh4.x);
            hv[b].y = fmaf(v.y, sc.y, sh4.y);
            hv[b].z = fmaf(v.z, sc.z, sh4.z);
            hv[b].w = fmaf(v.w, sc.w, sh4.w);
        }
#pragma unroll
        for (int c = 0; c < CC; c++) {
            float4 w = __ldg(w4 + (size_t)c * NI4 + i);
#pragma unroll
            for (int b = 0; b < BB; b++) {
                float t0 = fmaf(hv[b].x, w.x, hv[b].y * w.y);
                float t1 = fmaf(hv[b].z, w.z, hv[b].w * w.w);
                acc[b][c] += t0 + t1;
            }
        }
    }
#pragma unroll
    for (int b = 0; b < BB; b++)
#pragma unroll
        for (int c = 0; c < CC; c++)
#pragma unroll
            for (int off = 16; off > 0; off >>= 1)
                acc[b][c] += __shfl_xor_sync(0xFFFFFFFFu, acc[b][c], off);

    __shared__ float part[8][80];
    int w = threadIdx.x >> 5, lane = threadIdx.x & 31;
    if (lane == 0) {
#pragma unroll
        for (int b = 0; b < BB; b++)
#pragma unroll
            for (int c = 0; c < CC; c++) part[w][b * CC + c] = acc[b][c];
    }
    __syncthreads();
    int t = threadIdx.x;
    if (t < 80) {
        float s = 0.f;
#pragma unroll
        for (int ww = 0; ww < 8; ww++) s += part[ww][t];
        atomicAdd(&out[t], s);
    }
}

// ---------------- launch ----------------
extern "C" void kernel_launch(void* const* d_in, const int* in_sizes, int n_in,
                              void* d_out, int out_size) {
    const float* x     = (const float*)d_in[0];
    const int*   esrc  = (const int*)  d_in[1];
    const int*   edst  = (const int*)  d_in[2];
    const float* W1    = (const float*)d_in[3];
    const float* b1    = (const float*)d_in[4];
    const float* W2    = (const float*)d_in[5];
    const float* b2    = (const float*)d_in[6];
    const float* gamma = (const float*)d_in[7];
    const float* beta  = (const float*)d_in[8];
    const float* linW  = (const float*)d_in[9];
    const float* linb  = (const float*)d_in[10];
    float* out = (float*)d_out;

    k_degree <<<(BB * EE) / 256, 256>>>(esrc, edst);
    k_scan   <<<BB, 1024>>>();
    k_fill   <<<(BB * EE) / 256, 256>>>(esrc, edst, x);
    k_conv   <<<BB * (NN / 32), 256>>>(W1, b1, 0);   // launch idx 3 -> profiled
    k_conv   <<<BB * (NN / 32), 256>>>(W2, b2, 1);
    k_bnstats<<<256, 256>>>();
    k_bncoef <<<1, 128>>>(gamma, beta, linb, out);
    k_final  <<<296, 256>>>(linW, out);
}

// round 6
// speedup vs baseline: 1.1121x; 1.1121x over previous
#include <cuda_runtime.h>
#include <cstdint>

#define BB 8
#define NN 16384
#define FF 64
#define EE 262144
#define CC 10
#define BN_EPS 1e-5f

// ---------------- device scratch (no allocs; zero-initialized at load) ----------------
__device__ int    g_deg_out[BB * NN];      // zeroed by k_scan after use
__device__ int    g_deg_in [BB * NN];      // zeroed by k_scan after use
__device__ int    g_cursor [BB * NN];
__device__ float  g_rs_out [BB * NN];
__device__ float  g_rs_in  [BB * NN];
__device__ int    g_row_off[BB * (NN + 1)];
__device__ int    g_esrt   [(size_t)BB * EE];   // src indices sorted by dst
__device__ float  g_xs [(size_t)BB * NN * FF];  // x * rs_out  (conv1 input)
__device__ float  g_h1 [(size_t)BB * NN * FF];  // relu(conv1) * rs_out (conv2 input)
__device__ float  g_h2 [(size_t)BB * NN * FF];  // conv2 output
__device__ float  g_bn_sum [2 * FF];            // zeroed by k_bncoef after use
__device__ float  g_bn_coef[2 * FF];

// ---------------- kernels ----------------

__global__ void k_degree(const int* __restrict__ src, const int* __restrict__ dst) {
    int i = blockIdx.x * blockDim.x + threadIdx.x;   // BB*EE
    int b = i >> 18;                                  // EE = 2^18
    atomicAdd(&g_deg_out[b * NN + src[i]], 1);
    atomicAdd(&g_deg_in [b * NN + dst[i]], 1);
}

// one block per batch, 1024 threads, 16 nodes/thread.
__global__ __launch_bounds__(1024) void k_scan() {
    __shared__ int warpsum[32];
    int b = blockIdx.x, t = threadIdx.x;
    int lane = t & 31, wid = t >> 5;
    int base = b * NN + t * 16;
    int loc[16];
    int sum = 0;
#pragma unroll
    for (int i = 0; i < 16; i++) {
        int d = g_deg_in[base + i];
        loc[i] = sum; sum += d;
        g_rs_in[base + i] = rsqrtf((float)(d < 1 ? 1 : d));
        int dgo = g_deg_out[base + i];
        g_rs_out[base + i] = rsqrtf((float)(dgo < 1 ? 1 : dgo));
        g_deg_in[base + i]  = 0;                      // reset for next replay
        g_deg_out[base + i] = 0;
    }
    int v = sum;
#pragma unroll
    for (int off = 1; off < 32; off <<= 1) {
        int u = __shfl_up_sync(0xFFFFFFFFu, v, off);
        if (lane >= off) v += u;
    }
    if (lane == 31) warpsum[wid] = v;
    __syncthreads();
    if (wid == 0) {
        int w = warpsum[lane];
#pragma unroll
        for (int off = 1; off < 32; off <<= 1) {
            int u = __shfl_up_sync(0xFFFFFFFFu, w, off);
            if (lane >= off) w += u;
        }
        warpsum[lane] = w;
    }
    __syncthreads();
    int wbase = (wid == 0) ? 0 : warpsum[wid - 1];
    int excl  = wbase + v - sum;
    int ob = b * (NN + 1) + t * 16;
#pragma unroll
    for (int i = 0; i < 16; i++) {
        int o = excl + loc[i];
        g_row_off[ob + i] = o;
        g_cursor[base + i] = o;
    }
    if (t == 1023) g_row_off[b * (NN + 1) + NN] = excl + sum;
}

// bucket-fill sorted-by-dst src list (4B scatter) + prescale xs = x * rs_out
__global__ void k_fill(const int* __restrict__ src, const int* __restrict__ dst,
                       const float* __restrict__ x) {
    int i = blockIdx.x * blockDim.x + threadIdx.x;   // BB*EE == BB*NN*FF/4 == 2M
    int b = i >> 18;
    int s = src[i];
    int d = dst[i];
    int pos = atomicAdd(&g_cursor[b * NN + d], 1);
    g_esrt[(size_t)b * EE + pos] = s;

    float sc = g_rs_out[i >> 4];                      // (i*4)/FF
    float4 vx = __ldg((const float4*)x + i);
    vx.x *= sc; vx.y *= sc; vx.z *= sc; vx.w *= sc;
    ((float4*)g_xs)[i] = vx;
}

// Fused: CSR gather-sum + [32,64]x[64,64] GEMM + bias (+relu, +rs_out prescale for next conv)
// 512 threads, 32 nodes/CTA. Gather: 16 threads/node, one contiguous float4 each
// (full 128B-line utilization -> 2 L1 wavefronts per node-edge, the minimum).
// GEMM: threads 0..255 only, 2 nodes x 4 feats each (minimum LDS cycles).
__global__ __launch_bounds__(512) void k_conv(const float* __restrict__ W,
                                              const float* __restrict__ bias,
                                              int phase) {
    __shared__ float sW[64 * 64];
    __shared__ float sT[64][33];                      // [k][node], padded

    const float* in  = (phase == 0) ? g_xs : g_h1;
    float*       out = (phase == 0) ? g_h1 : g_h2;

    int t  = threadIdx.x;
    int cb = blockIdx.x;
    int b  = cb >> 9;                                 // 512 CTAs per batch
    int n0 = (cb & 511) << 5;

    for (int i = t; i < 64 * 64; i += 512) sW[i] = W[i];

    // ---- gather: 16 threads/node, 4 contiguous features each ----
    int nl = t >> 4;                                  // 0..31
    int f0 = (t & 15) << 2;                           // 0,4,...,60
    int n  = n0 + nl;
    const float* inb = in + (size_t)b * NN * FF;
    const int*   es  = g_esrt + (size_t)b * EE;
    int r0 = g_row_off[b * (NN + 1) + n];
    int r1 = g_row_off[b * (NN + 1) + n + 1];

    float4 a = make_float4(0.f, 0.f, 0.f, 0.f);
    int e = r0;
    for (; e + 4 <= r1; e += 4) {
        int s0 = __ldg(es + e);
        int s1 = __ldg(es + e + 1);
        int s2 = __ldg(es + e + 2);
        int s3 = __ldg(es + e + 3);
        float4 v0 = __ldg((const float4*)(inb + (size_t)s0 * FF + f0));
        float4 v1 = __ldg((const float4*)(inb + (size_t)s1 * FF + f0));
        float4 v2 = __ldg((const float4*)(inb + (size_t)s2 * FF + f0));
        float4 v3 = __ldg((const float4*)(inb + (size_t)s3 * FF + f0));
        a.x += (v0.x + v1.x) + (v2.x + v3.x);
        a.y += (v0.y + v1.y) + (v2.y + v3.y);
        a.z += (v0.z + v1.z) + (v2.z + v3.z);
        a.w += (v0.w + v1.w) + (v2.w + v3.w);
    }
    for (; e < r1; e++) {
        int s0 = __ldg(es + e);
        float4 v0 = __ldg((const float4*)(inb + (size_t)s0 * FF + f0));
        a.x += v0.x; a.y += v0.y; a.z += v0.z; a.w += v0.w;
    }
    float si = g_rs_in[b * NN + n];
    sT[f0 + 0][nl] = a.x * si;
    sT[f0 + 1][nl] = a.y * si;
    sT[f0 + 2][nl] = a.z * si;
    sT[f0 + 3][nl] = a.w * si;
    __syncthreads();

    // ---- GEMM on first 256 threads: 2 nodes x 4 features each ----
    if (t < 256) {
        int nn = (t >> 4) << 1;
        int q  = (t & 15) << 2;
        float4 c0 = make_float4(0.f, 0.f, 0.f, 0.f);
        float4 c1 = make_float4(0.f, 0.f, 0.f, 0.f);
#pragma unroll
        for (int k = 0; k < 64; k++) {
            float x0 = sT[k][nn];
            float x1 = sT[k][nn + 1];
            float4 w = *(const float4*)&sW[k * 64 + q];
            c0.x = fmaf(x0, w.x, c0.x); c0.y = fmaf(x0, w.y, c0.y);
            c0.z = fmaf(x0, w.z, c0.z); c0.w = fmaf(x0, w.w, c0.w);
            c1.x = fmaf(x1, w.x, c1.x); c1.y = fmaf(x1, w.y, c1.y);
            c1.z = fmaf(x1, w.z, c1.z); c1.w = fmaf(x1, w.w, c1.w);
        }
        float4 bv = __ldg((const float4*)(bias + q));
        c0.x += bv.x; c0.y += bv.y; c0.z += bv.z; c0.w += bv.w;
        c1.x += bv.x; c1.y += bv.y; c1.z += bv.z; c1.w += bv.w;
        if (phase == 0) {
            float s0 = g_rs_out[b * NN + n0 + nn];
            float s1 = g_rs_out[b * NN + n0 + nn + 1];
            c0.x = fmaxf(c0.x, 0.f) * s0; c0.y = fmaxf(c0.y, 0.f) * s0;
            c0.z = fmaxf(c0.z, 0.f) * s0; c0.w = fmaxf(c0.w, 0.f) * s0;
            c1.x = fmaxf(c1.x, 0.f) * s1; c1.y = fmaxf(c1.y, 0.f) * s1;
            c1.z = fmaxf(c1.z, 0.f) * s1; c1.w = fmaxf(c1.w, 0.f) * s1;
        }
        *(float4*)(out + ((size_t)b * NN + n0 + nn)     * FF + q) = c0;
        *(float4*)(out + ((size_t)b * NN + n0 + nn + 1) * FF + q) = c1;
    }
}

__global__ __launch_bounds__(256) void k_bnstats() {
    int tid = blockIdx.x * 256 + threadIdx.x;
    int stride = gridDim.x * 256;                    // multiple of 16
    const float4* h = (const float4*)g_h2;
    float4 s = make_float4(0.f, 0.f, 0.f, 0.f);
    float4 q = make_float4(0.f, 0.f, 0.f, 0.f);
    for (int i = tid; i < BB * NN * FF / 4; i += stride) {
        float4 v = __ldg(h + i);
        s.x += v.x; s.y += v.y; s.z += v.z; s.w += v.w;
        q.x = fmaf(v.x, v.x, q.x); q.y = fmaf(v.y, v.y, q.y);
        q.z = fmaf(v.z, v.z, q.z); q.w = fmaf(v.w, v.w, q.w);
    }
    int f0 = (tid & 15) * 4;
    __shared__ float sh[128];
    if (threadIdx.x < 128) sh[threadIdx.x] = 0.f;
    __syncthreads();
    atomicAdd(&sh[f0 + 0], s.x); atomicAdd(&sh[f0 + 1], s.y);
    atomicAdd(&sh[f0 + 2], s.z); atomicAdd(&sh[f0 + 3], s.w);
    atomicAdd(&sh[64 + f0 + 0], q.x); atomicAdd(&sh[64 + f0 + 1], q.y);
    atomicAdd(&sh[64 + f0 + 2], q.z); atomicAdd(&sh[64 + f0 + 3], q.w);
    __syncthreads();
    if (threadIdx.x < 128) atomicAdd(&g_bn_sum[threadIdx.x], sh[threadIdx.x]);
}

// coef computation + bn_sum reset + output bias init (128 threads)
__global__ void k_bncoef(const float* __restrict__ gamma, const float* __restrict__ beta,
                         const float* __restrict__ lin_b, float* __restrict__ out) {
    int t = threadIdx.x;
    if (t < 64) {
        const float inv_n = 1.0f / (float)(BB * NN);
        float s  = g_bn_sum[t];
        float s2 = g_bn_sum[64 + t];
        float mean = s * inv_n;
        float var  = s2 * inv_n - mean * mean;
        float scale = gamma[t] * rsqrtf(var + BN_EPS);
        g_bn_coef[t]      = scale;
        g_bn_coef[64 + t] = beta[t] - mean * scale;
        g_bn_sum[t] = 0.0f;
        g_bn_sum[64 + t] = 0.0f;
    }
    if (t < 80) out[t] = lin_b[t % CC];
}

// out[b][c] += sum_i (h2[b][i]*scale[f]+shift[f]) * lin_W[c][i]
__global__ __launch_bounds__(256) void k_final(const float* __restrict__ linW,
                                               float* __restrict__ out) {
    __shared__ float cf[128];
    if (threadIdx.x < 128) cf[threadIdx.x] = g_bn_coef[threadIdx.x];
    __syncthreads();

    int tid = blockIdx.x * 256 + threadIdx.x;
    int stride = gridDim.x * 256;                    // multiple of 16
    const int NI4 = NN * FF / 4;
    float acc[BB][CC];
#pragma unroll
    for (int b = 0; b < BB; b++)
#pragma unroll
        for (int c = 0; c < CC; c++) acc[b][c] = 0.f;

    const float4* h4 = (const float4*)g_h2;
    const float4* w4 = (const float4*)linW;
    for (int i = tid; i < NI4; i += stride) {
        int f0 = (i & 15) * 4;
        float4 sc  = *(const float4*)&cf[f0];
        float4 sh4 = *(const float4*)&cf[64 + f0];
        float4 hv[BB];
#pragma unroll
        for (int b = 0; b < BB; b++) {
            float4 v = __ldg(h4 + (size_t)b * NI4 + i);
            hv[b].x = fmaf(v.x, sc.x, sh4.x);
            hv[b].y = fmaf(v.y, sc.y, sh4.y);
            hv[b].z = fmaf(v.z, sc.z, sh4.z);
            hv[b].w = fmaf(v.w, sc.w, sh4.w);
        }
#pragma unroll
        for (int c = 0; c < CC; c++) {
            float4 w = __ldg(w4 + (size_t)c * NI4 + i);
#pragma unroll
            for (int b = 0; b < BB; b++) {
                float t0 = fmaf(hv[b].x, w.x, hv[b].y * w.y);
                float t1 = fmaf(hv[b].z, w.z, hv[b].w * w.w);
                acc[b][c] += t0 + t1;
            }
        }
    }
#pragma unroll
    for (int b = 0; b < BB; b++)
#pragma unroll
        for (int c = 0; c < CC; c++)
#pragma unroll
            for (int off = 16; off > 0; off >>= 1)
                acc[b][c] += __shfl_xor_sync(0xFFFFFFFFu, acc[b][c], off);

    __shared__ float part[8][80];
    int w = threadIdx.x >> 5, lane = threadIdx.x & 31;
    if (lane == 0) {
#pragma unroll
        for (int b = 0; b < BB; b++)
#pragma unroll
            for (int c = 0; c < CC; c++) part[w][b * CC + c] = acc[b][c];
    }
    __syncthreads();
    int t = threadIdx.x;
    if (t < 80) {
        float s = 0.f;
#pragma unroll
        for (int ww = 0; ww < 8; ww++) s += part[ww][t];
        atomicAdd(&out[t], s);
    }
}

// ---------------- launch ----------------
extern "C" void kernel_launch(void* const* d_in, const int* in_sizes, int n_in,
                              void* d_out, int out_size) {
    const float* x     = (const float*)d_in[0];
    const int*   esrc  = (const int*)  d_in[1];
    const int*   edst  = (const int*)  d_in[2];
    const float* W1    = (const float*)d_in[3];
    const float* b1    = (const float*)d_in[4];
    const float* W2    = (const float*)d_in[5];
    const float* b2    = (const float*)d_in[6];
    const float* gamma = (const float*)d_in[7];
    const float* beta  = (const float*)d_in[8];
    const float* linW  = (const float*)d_in[9];
    const float* linb  = (const float*)d_in[10];
    float* out = (float*)d_out;

    k_degree <<<(BB * EE) / 256, 256>>>(esrc, edst);
    k_scan   <<<BB, 1024>>>();
    k_fill   <<<(BB * EE) / 256, 256>>>(esrc, edst, x);
    k_conv   <<<BB * (NN / 32), 512>>>(W1, b1, 0);   // launch idx 3 -> profiled
    k_conv   <<<BB * (NN / 32), 512>>>(W2, b2, 1);
    k_bnstats<<<256, 256>>>();
    k_bncoef <<<1, 128>>>(gamma, beta, linb, out);
    k_final  <<<296, 256>>>(linW, out);
}